// round 2
// baseline (speedup 1.0000x reference)
#include <cuda_runtime.h>
#include <math.h>

// Problem constants
#define BB   2
#define AA   3
#define NCLS 3
#define CC   (NCLS*AA)   // 9 channels
#define DD   64
#define HH   128
#define WW   128
#define MM   128
#define EPSF 1e-4f

// Tiling for the neg (NMS + focal) kernel
#define HT     16                // output rows per block tile
#define DSPLIT 2
#define DCHUNK (DD/DSPLIT)       // 32 d-slices per block

__device__ __forceinline__ float warp_sum(float v) {
    #pragma unroll
    for (int o = 16; o; o >>= 1) v += __shfl_down_sync(0xffffffffu, v, o);
    return v;
}

// ---------------------------------------------------------------------------
// Neg kernel: per-element sigmoid focal negative loss with 3x3x3 NMS filter.
// Block: (128, 4) = 512 threads. Tile: HT rows x full W x DCHUNK d-slices for
// one (b, c) channel. Rolling 3-plane smem buffer along D; dmax = elementwise
// max of the 3 planes; output max = 3x3 window over dmax.
// ---------------------------------------------------------------------------
__global__ __launch_bounds__(512, 2)
void neg_kernel(const float* __restrict__ logits,
                const float* __restrict__ prob_gt,
                float* __restrict__ out)
{
    __shared__ float plane[3][HT + 2][WW];
    __shared__ float dmax[HT + 2][WW];
    __shared__ float redl[16], redc[16];

    const int bc = blockIdx.x;            // 0..17
    const int b  = bc / CC;
    const int c  = bc % CC;
    const int a  = c % AA;                // negmask uses prob_gt[b, a]
    const int h0 = blockIdx.y * HT;
    const int d0 = blockIdx.z * DCHUNK;
    const int tx = threadIdx.x;           // w (0..127)
    const int ty = threadIdx.y;           // 0..3

    const float NEG_INF = __int_as_float(0xff800000);
    const float* chan = logits + (size_t)(b * CC + c) * DD * HH * WW;
    const float* pga  = prob_gt + (size_t)(b * AA + a) * DD * HH * WW;

    // plane slot for d-index pd is ((pd+1) mod 3); preload pd = d0-1, d0
    {
        // pd = d0 - 1
        int pd = d0 - 1;
        int slot = (pd + 1 + 3) % 3;
        bool vd = (pd >= 0);
        #pragma unroll
        for (int r = ty; r < HT + 2; r += 4) {
            int h = h0 - 1 + r;
            float v = NEG_INF;
            if (vd && h >= 0 && h < HH) v = chan[((size_t)pd * HH + h) * WW + tx];
            plane[slot][r][tx] = v;
        }
        // pd = d0
        pd = d0;
        slot = (pd + 1) % 3;
        #pragma unroll
        for (int r = ty; r < HT + 2; r += 4) {
            int h = h0 - 1 + r;
            float v = NEG_INF;
            if (h >= 0 && h < HH) v = chan[((size_t)pd * HH + h) * WW + tx];
            plane[slot][r][tx] = v;
        }
    }

    float loss = 0.0f, cnt = 0.0f;

    for (int d = d0; d < d0 + DCHUNK; ++d) {
        // load plane d+1 into slot (d+2)%3
        {
            int pd = d + 1;
            int slot = (pd + 1) % 3;
            bool vd = (pd < DD);
            #pragma unroll
            for (int r = ty; r < HT + 2; r += 4) {
                int h = h0 - 1 + r;
                float v = NEG_INF;
                if (vd && h >= 0 && h < HH) v = chan[((size_t)pd * HH + h) * WW + tx];
                plane[slot][r][tx] = v;
            }
        }
        __syncthreads();

        // dmax = elementwise max over the 3 resident planes
        #pragma unroll
        for (int r = ty; r < HT + 2; r += 4) {
            dmax[r][tx] = fmaxf(fmaxf(plane[0][r][tx], plane[1][r][tx]),
                                plane[2][r][tx]);
        }
        __syncthreads();

        const int cs = (d + 1) % 3;       // slot holding plane d (center)
        #pragma unroll
        for (int k = 0; k < 4; ++k) {
            const int lr = 1 + ty + 4 * k;        // 1..16
            float m = fmaxf(fmaxf(dmax[lr - 1][tx], dmax[lr][tx]),
                            dmax[lr + 1][tx]);
            if (tx > 0) {
                m = fmaxf(m, fmaxf(fmaxf(dmax[lr - 1][tx - 1], dmax[lr][tx - 1]),
                                   dmax[lr + 1][tx - 1]));
            }
            if (tx < WW - 1) {
                m = fmaxf(m, fmaxf(fmaxf(dmax[lr - 1][tx + 1], dmax[lr][tx + 1]),
                                   dmax[lr + 1][tx + 1]));
            }
            const float cen = plane[cs][lr][tx];
            if (m == cen) {                        // pooled == logits (exact)
                const int h = h0 + lr - 1;
                const float pg = pga[((size_t)d * HH + h) * WW + tx];
                if (pg == -1.0f) {
                    float p = 1.0f / (1.0f + expf(-cen));
                    p = fminf(fmaxf(p, EPSF), 1.0f - EPSF);
                    if (p > EPSF) {                // thresh_filter
                        const float w = p * p;     // p^ALPHA, ALPHA=2
                        loss -= logf(1.0f - p) * w;
                        cnt  += w;
                    }
                }
            }
        }
        // no trailing sync needed: next load writes the slot of plane d-1,
        // which this iteration's output phase never reads; dmax is only
        // rewritten after the post-load __syncthreads().
    }

    // block reduction (16 warps)
    const int tid  = ty * 128 + tx;
    const int wid  = tid >> 5;
    const int lane = tid & 31;
    loss = warp_sum(loss);
    cnt  = warp_sum(cnt);
    if (lane == 0) { redl[wid] = loss; redc[wid] = cnt; }
    __syncthreads();
    if (wid == 0) {
        float l  = (lane < 16) ? redl[lane] : 0.0f;
        float cv = (lane < 16) ? redc[lane] : 0.0f;
        l  = warp_sum(l);
        cv = warp_sum(cv);
        if (lane == 0) {
            atomicAdd(&out[1], l);    // loss_neg
            atomicAdd(&out[4], cv);   // count_neg
        }
    }
}

// ---------------------------------------------------------------------------
// Pos / other kernel: B blocks x M threads (one thread per ground-truth slot).
// NOTE: coord_gt is int32 on device (JAX x64 disabled downcasts int64->int32).
// ---------------------------------------------------------------------------
__global__ void pos_kernel(const float* __restrict__ logits,
                           const float* __restrict__ prob_gt,
                           const int* __restrict__ coord,
                           const float* __restrict__ wcls,
                           float* __restrict__ out)
{
    const int b = blockIdx.x;
    const int m = threadIdx.x;            // 0..127

    __shared__ int present[NCLS];
    __shared__ float r0[4], r1[4], r2[4], r3[4];

    if (m < NCLS) present[m] = 0;
    __syncthreads();

    const int* cg = coord + ((size_t)b * MM + m) * 4;
    const int c0 = cg[0];
    const bool valid = c0 > -1;
    const int a = valid ? c0    : 0;
    const int d = valid ? cg[1] : 0;
    const int h = valid ? cg[2] : 0;
    const int w = valid ? cg[3] : 0;

    const float pgv = prob_gt[(((size_t)(b * AA + a) * DD + d) * HH + h) * WW + w];
    int cls = valid ? ((int)pgv - 1) : 0;
    cls = min(max(cls, 0), NCLS - 1);     // defensive clamp
    if (valid) present[cls] = 1;          // benign race: same value
    __syncthreads();

    const float vf = valid ? 1.0f : 0.0f;

    auto getp = [&](int ch) -> float {
        const float x = logits[(((size_t)(b * CC + ch) * DD + d) * HH + h) * WW + w];
        float p = 1.0f / (1.0f + expf(-x));
        return fminf(fmaxf(p, EPSF), 1.0f - EPSF);
    };

    const float pt   = getp(cls * AA + a);
    const float omt  = 1.0f - pt;
    const float wpos = omt * omt * wcls[cls] * vf;
    float lpos = -logf(pt) * wpos;
    float cpos = wpos;

    float loth = 0.0f, coth = 0.0f;
    const float thr = pt - 0.1f;
    const float ptgate = (pt > 0.5f) ? 1.0f : 0.0f;
    #pragma unroll
    for (int k = 0; k < NCLS; ++k) {
        const float po = getp(k * AA + a);
        float wo = fmaxf(po - thr, 0.0f);
        wo *= (po > 0.5f) ? 1.0f : 0.0f;
        wo *= ptgate;
        if (present[k]) wo = 0.0f;        // zero_rows
        wo *= vf;
        loth += -logf(1.0f - po) * wo;
        coth += wo;
    }

    // block reduction over 4 warps
    const int wid = m >> 5, lane = m & 31;
    lpos = warp_sum(lpos);
    cpos = warp_sum(cpos);
    loth = warp_sum(loth);
    coth = warp_sum(coth);
    if (lane == 0) { r0[wid] = lpos; r1[wid] = cpos; r2[wid] = loth; r3[wid] = coth; }
    __syncthreads();
    if (m == 0) {
        float s0 = 0, s1 = 0, s2 = 0, s3 = 0;
        #pragma unroll
        for (int i = 0; i < 4; ++i) { s0 += r0[i]; s1 += r1[i]; s2 += r2[i]; s3 += r3[i]; }
        atomicAdd(&out[0], s0);   // l_pos
        atomicAdd(&out[3], s1);   // c_pos
        atomicAdd(&out[2], s2);   // l_oth
        atomicAdd(&out[5], s3);   // c_oth
    }
}

extern "C" void kernel_launch(void* const* d_in, const int* in_sizes, int n_in,
                              void* d_out, int out_size)
{
    const float* logits  = (const float*)d_in[0];
    const float* prob_gt = (const float*)d_in[1];
    const int*   coord   = (const int*)d_in[2];
    const float* wcls    = (const float*)d_in[3];
    float* out = (float*)d_out;

    cudaMemsetAsync(out, 0, (size_t)out_size * sizeof(float));

    dim3 grid(BB * CC, HH / HT, DSPLIT);   // 18 x 8 x 2 = 288 blocks
    dim3 block(128, 4);                    // 512 threads
    neg_kernel<<<grid, block>>>(logits, prob_gt, out);

    pos_kernel<<<BB, MM>>>(logits, prob_gt, coord, wcls, out);
}

// round 4
// speedup vs baseline: 2.8153x; 2.8153x over previous
#include <cuda_runtime.h>
#include <math.h>

// Problem constants
#define BB   2
#define AA   3
#define NCLS 3
#define CC   (NCLS*AA)   // 9 channels
#define DD   64
#define HH   128
#define WW   128
#define MM   128
#define EPSF 1e-4f

#define HT     16                // output rows per block tile
#define DSPLIT 2
#define DCHUNK (DD/DSPLIT)       // 32 d-slices per block
#define TYN    (HT + 2)          // 18 rows incl. halo
#define NWARP  TYN               // one warp per row (32 lanes x float4 = 128 w)

#define NEG_INF __int_as_float(0xff800000)

__device__ __forceinline__ float warp_sum(float v) {
    #pragma unroll
    for (int o = 16; o; o >>= 1) v += __shfl_down_sync(0xffffffffu, v, o);
    return v;
}

__device__ __forceinline__ float4 fmax4(float4 a, float4 b) {
    return make_float4(fmaxf(a.x, b.x), fmaxf(a.y, b.y),
                       fmaxf(a.z, b.z), fmaxf(a.w, b.w));
}

// w-direction 3-window max of a row held as float4 per lane (warp-wide row).
__device__ __forceinline__ float4 wmax3(float4 v, int lane) {
    float left  = __shfl_up_sync(0xffffffffu, v.w, 1);
    float right = __shfl_down_sync(0xffffffffu, v.x, 1);
    if (lane == 0)  left  = NEG_INF;
    if (lane == 31) right = NEG_INF;
    float4 r;
    r.x = fmaxf(fmaxf(left, v.x), v.y);
    r.y = fmaxf(fmaxf(v.x, v.y), v.z);
    r.z = fmaxf(fmaxf(v.y, v.z), v.w);
    r.w = fmaxf(fmaxf(v.z, v.w), right);
    return r;
}

__global__ __launch_bounds__(32 * TYN, 2)
void focal_kernel(const float* __restrict__ logits,
                  const float* __restrict__ prob_gt,
                  const int* __restrict__ coord,
                  const float* __restrict__ wcls,
                  float* __restrict__ out)
{
    __shared__ float4 rbuf[2][TYN][32];       // per-plane row-wmax, double-buffered
    __shared__ float  redl[NWARP], redc[NWARP];

    const int lane = threadIdx.x;             // 0..31 (w4)
    const int ty   = threadIdx.y;             // 0..17
    const int tid  = ty * 32 + lane;

    // ======================= POS / OTHER path (one block) ===================
    if (blockIdx.x == BB * CC) {
        if (blockIdx.y != 0 || blockIdx.z != 0) return;

        __shared__ int   present[BB][NCLS];
        __shared__ float rp0[NWARP], rp1[NWARP], rp2[NWARP], rp3[NWARP];

        if (tid < BB * NCLS) present[tid / NCLS][tid % NCLS] = 0;
        __syncthreads();

        const bool active = tid < BB * MM;    // 256 threads do work
        const int b = tid >> 7;
        const int m = tid & (MM - 1);

        float lpos = 0.f, cpos = 0.f, loth = 0.f, coth = 0.f;
        int cls = 0, a = 0, d = 0, h = 0, w = 0;
        bool valid = false;
        if (active) {
            const int* cg = coord + ((size_t)b * MM + m) * 4;
            const int c0 = cg[0];
            valid = c0 > -1;
            a = valid ? c0    : 0;
            d = valid ? cg[1] : 0;
            h = valid ? cg[2] : 0;
            w = valid ? cg[3] : 0;
            const float pgv = prob_gt[(((size_t)(b * AA + a) * DD + d) * HH + h) * WW + w];
            cls = valid ? ((int)pgv - 1) : 0;
            cls = min(max(cls, 0), NCLS - 1);
            if (valid) present[b][cls] = 1;   // benign race
        }
        __syncthreads();

        if (active) {
            const float vf = valid ? 1.0f : 0.0f;
            auto getp = [&](int ch) -> float {
                const float x = logits[(((size_t)(b * CC + ch) * DD + d) * HH + h) * WW + w];
                float p = 1.0f / (1.0f + expf(-x));
                return fminf(fmaxf(p, EPSF), 1.0f - EPSF);
            };
            const float pt   = getp(cls * AA + a);
            const float omt  = 1.0f - pt;
            const float wpos = omt * omt * wcls[cls] * vf;
            lpos = -logf(pt) * wpos;
            cpos = wpos;

            const float thr = pt - 0.1f;
            const float ptgate = (pt > 0.5f) ? 1.0f : 0.0f;
            #pragma unroll
            for (int k = 0; k < NCLS; ++k) {
                const float po = getp(k * AA + a);
                float wo = fmaxf(po - thr, 0.0f);
                wo *= (po > 0.5f) ? 1.0f : 0.0f;
                wo *= ptgate;
                if (present[b][k]) wo = 0.0f;
                wo *= vf;
                loth += -logf(1.0f - po) * wo;
                coth += wo;
            }
        }

        const int wid = tid >> 5, ln = tid & 31;
        lpos = warp_sum(lpos); cpos = warp_sum(cpos);
        loth = warp_sum(loth); coth = warp_sum(coth);
        if (ln == 0) { rp0[wid] = lpos; rp1[wid] = cpos; rp2[wid] = loth; rp3[wid] = coth; }
        __syncthreads();
        if (tid == 0) {
            float s0 = 0, s1 = 0, s2 = 0, s3 = 0;
            #pragma unroll
            for (int i = 0; i < NWARP; ++i) { s0 += rp0[i]; s1 += rp1[i]; s2 += rp2[i]; s3 += rp3[i]; }
            atomicAdd(&out[0], s0);   // l_pos
            atomicAdd(&out[3], s1);   // c_pos
            atomicAdd(&out[2], s2);   // l_oth
            atomicAdd(&out[5], s3);   // c_oth
        }
        return;
    }

    // ============================ NEG path ==================================
    const int bc = blockIdx.x;            // 0..17
    const int b  = bc / CC;
    const int c  = bc % CC;
    const int a  = c % AA;                // negmask uses prob_gt[b, a]
    const int h0 = blockIdx.y * HT;
    const int d0 = blockIdx.z * DCHUNK;

    const int  h    = h0 - 1 + ty;        // -1..128
    const bool hin  = (h >= 0) && (h < HH);
    const bool isout = (ty >= 1) && (ty <= HT);   // h in [h0, h0+15], always in range

    const float* chan = logits  + (size_t)(b * CC + c) * DD * HH * WW;
    const float* pga  = prob_gt + (size_t)(b * AA + a) * DD * HH * WW;
    const float* rowp = chan + (size_t)h * WW + lane * 4;   // valid iff hin
    const float* pgp  = pga  + (size_t)h * WW + lane * 4;   // valid iff isout

    const float4 ninf4 = make_float4(NEG_INF, NEG_INF, NEG_INF, NEG_INF);

    auto load_plane = [&](int pd) -> float4 {
        if (hin && pd >= 0 && pd < DD)
            return *(const float4*)(rowp + (size_t)pd * HH * WW);
        return ninf4;
    };

    float4 vcur, hm_m1, hm_0;

    // ---- prologue: plane d0-1 ----
    {
        float4 v = load_plane(d0 - 1);
        rbuf[(d0 - 1) & 1][ty][lane] = wmax3(v, lane);
        __syncthreads();
        if (isout) {
            const int par = (d0 - 1) & 1;
            hm_m1 = fmax4(fmax4(rbuf[par][ty - 1][lane], rbuf[par][ty][lane]),
                          rbuf[par][ty + 1][lane]);
        }
    }
    // ---- prologue: plane d0 ----
    {
        vcur = load_plane(d0);
        rbuf[d0 & 1][ty][lane] = wmax3(vcur, lane);
        __syncthreads();
        if (isout) {
            const int par = d0 & 1;
            hm_0 = fmax4(fmax4(rbuf[par][ty - 1][lane], rbuf[par][ty][lane]),
                         rbuf[par][ty + 1][lane]);
        }
    }

    float loss = 0.0f, cnt = 0.0f;

    for (int d = d0; d < d0 + DCHUNK; ++d) {
        // prefetch prob_gt for current d (consumed after barrier)
        float4 pg = ninf4;
        if (isout) pg = *(const float4*)(pgp + (size_t)d * HH * WW);

        // pipeline: load plane d+1, publish its row-wmax
        float4 vnext = load_plane(d + 1);
        const int par = (d + 1) & 1;
        rbuf[par][ty][lane] = wmax3(vnext, lane);
        __syncthreads();

        if (isout) {
            float4 hm_p1 = fmax4(fmax4(rbuf[par][ty - 1][lane], rbuf[par][ty][lane]),
                                 rbuf[par][ty + 1][lane]);
            float4 m = fmax4(fmax4(hm_m1, hm_0), hm_p1);

            // per-component focal negative loss
            {
                const float mm[4]  = { m.x, m.y, m.z, m.w };
                const float cc4[4] = { vcur.x, vcur.y, vcur.z, vcur.w };
                const float pp[4]  = { pg.x, pg.y, pg.z, pg.w };
                #pragma unroll
                for (int i = 0; i < 4; ++i) {
                    if (mm[i] == cc4[i] && pp[i] == -1.0f) {
                        float p = 1.0f / (1.0f + expf(-cc4[i]));
                        p = fminf(fmaxf(p, EPSF), 1.0f - EPSF);
                        if (p > EPSF) {
                            const float w = p * p;      // p^ALPHA, ALPHA=2
                            loss -= logf(1.0f - p) * w;
                            cnt  += w;
                        }
                    }
                }
            }
            hm_m1 = hm_0;
            hm_0  = hm_p1;
        }
        vcur = vnext;
    }

    // block reduction (18 warps; warp == one ty row)
    loss = warp_sum(loss);
    cnt  = warp_sum(cnt);
    if (lane == 0) { redl[ty] = loss; redc[ty] = cnt; }
    __syncthreads();
    if (tid == 0) {
        float l = 0.f, cv = 0.f;
        #pragma unroll
        for (int i = 0; i < NWARP; ++i) { l += redl[i]; cv += redc[i]; }
        atomicAdd(&out[1], l);    // loss_neg
        atomicAdd(&out[4], cv);   // count_neg
    }
}

extern "C" void kernel_launch(void* const* d_in, const int* in_sizes, int n_in,
                              void* d_out, int out_size)
{
    const float* logits  = (const float*)d_in[0];
    const float* prob_gt = (const float*)d_in[1];
    const int*   coord   = (const int*)d_in[2];
    const float* wcls    = (const float*)d_in[3];
    float* out = (float*)d_out;

    cudaMemsetAsync(out, 0, (size_t)out_size * sizeof(float));

    // x: 18 neg channel-blocks + 1 pos block; y: h tiles; z: d split
    dim3 grid(BB * CC + 1, HH / HT, DSPLIT);
    dim3 block(32, TYN);                   // 576 threads
    focal_kernel<<<grid, block>>>(logits, prob_gt, coord, wcls, out);
}